// round 16
// baseline (speedup 1.0000x reference)
#include <cuda_runtime.h>
#include <cuda_bf16.h>
#include <math.h>
#include <float.h>
#include <stdint.h>

// Problem constants
#define Bz   4
#define Nn   4096
#define DIMc 1024
#define Hh   16
#define DHh  64
#define Mm   32

#define NORMALIZER 0.3535533905932738f   // 64^-0.25
#define DIAGC      0.0625f               // 0.5 * 64^-0.5
#define RATIO      0.17677669529663687f  // 32^-0.5
#define FEPS       1e-4f

#define NSEG 16

// ---------------- scratch (device globals) -------------
__device__ float g_v   [Bz*Nn*DIMc];
__device__ float g_qf  [Bz*Hh*Nn*Mm];
__device__ float g_kf  [Bz*Hh*Nn*Mm];     // raw dd - diag (exp applied at use)
__device__ float g_kmax[Bz*Hh];
__device__ float g_kcs [Bz*Hh*Mm];
__device__ float g_ctx [Bz*Hh*Mm*DHh];
__device__ float g_ctxp[Bz*Hh*NSEG*Mm*DHh];

__device__ __nv_bfloat16 g_xh [Bz*Nn*DIMc];
__device__ __nv_bfloat16 g_xl [Bz*Nn*DIMc];
__device__ __nv_bfloat16 g_wth[4*DIMc*DIMc];
__device__ __nv_bfloat16 g_wtl[4*DIMc*DIMc];

// ==================== helpers ====================
__device__ __forceinline__ uint32_t smem_u32(const void* p) {
    uint32_t a;
    asm("{ .reg .u64 t; cvta.to.shared.u64 t, %1; cvt.u32.u64 %0, t; }" : "=r"(a) : "l"(p));
    return a;
}
__device__ __forceinline__ void cp_async16_cg(uint32_t saddr, const void* gaddr) {
    asm volatile("cp.async.cg.shared.global [%0], [%1], 16;" :: "r"(saddr), "l"(gaddr));
}
__device__ __forceinline__ void cp_async16_ca(uint32_t saddr, const void* gaddr) {
    asm volatile("cp.async.ca.shared.global [%0], [%1], 16;" :: "r"(saddr), "l"(gaddr));
}
__device__ __forceinline__ void cp_commit() {
    asm volatile("cp.async.commit_group;" ::: "memory");
}
__device__ __forceinline__ void cp_wait1() {
    asm volatile("cp.async.wait_group 1;" ::: "memory");
}
__device__ __forceinline__ void ldmatrix_x4(uint32_t* r, uint32_t addr) {
    asm volatile("ldmatrix.sync.aligned.m8n8.x4.shared.b16 {%0,%1,%2,%3}, [%4];"
                 : "=r"(r[0]), "=r"(r[1]), "=r"(r[2]), "=r"(r[3]) : "r"(addr));
}
__device__ __forceinline__ void mma16816(float* d, const uint32_t* a, const uint32_t* b) {
    asm volatile(
        "mma.sync.aligned.m16n8k16.row.col.f32.bf16.bf16.f32 "
        "{%0,%1,%2,%3}, {%4,%5,%6,%7}, {%8,%9}, {%0,%1,%2,%3};"
        : "+f"(d[0]), "+f"(d[1]), "+f"(d[2]), "+f"(d[3])
        : "r"(a[0]), "r"(a[1]), "r"(a[2]), "r"(a[3]), "r"(b[0]), "r"(b[1]));
}
__device__ __forceinline__ void atomic_fmax(float* addr, float m) {
    int* ia = (int*)addr;
    int old = *ia;
    while (__int_as_float(old) < m) {
        int assumed = old;
        old = atomicCAS(ia, assumed, __float_as_int(m));
        if (old == assumed) break;
    }
}

// ==================== split conversion kernels ====================
__global__ __launch_bounds__(256)
void split_kernel(const float4* __restrict__ in,
                  __nv_bfloat162* __restrict__ hi, __nv_bfloat162* __restrict__ lo)
{
    int i = blockIdx.x * 256 + threadIdx.x;
    float4 v = in[i];
    __nv_bfloat162 h0, h1, l0, l1;
    h0.x = __float2bfloat16_rn(v.x); l0.x = __float2bfloat16_rn(v.x - __bfloat162float(h0.x));
    h0.y = __float2bfloat16_rn(v.y); l0.y = __float2bfloat16_rn(v.y - __bfloat162float(h0.y));
    h1.x = __float2bfloat16_rn(v.z); l1.x = __float2bfloat16_rn(v.z - __bfloat162float(h1.x));
    h1.y = __float2bfloat16_rn(v.w); l1.y = __float2bfloat16_rn(v.w - __bfloat162float(h1.y));
    hi[2*i] = h0; hi[2*i+1] = h1;
    lo[2*i] = l0; lo[2*i+1] = l1;
}

__global__ __launch_bounds__(256)
void splitT_kernel(const float* __restrict__ W,
                   __nv_bfloat16* __restrict__ th, __nv_bfloat16* __restrict__ tl)
{
    __shared__ float t[32][33];
    int tx = threadIdx.x & 31, ty = threadIdx.x >> 5;
    int k0 = blockIdx.y * 32, n0 = blockIdx.x * 32;
#pragma unroll
    for (int r = 0; r < 4; r++)
        t[ty + r*8][tx] = W[(size_t)(k0 + ty + r*8) * DIMc + n0 + tx];
    __syncthreads();
#pragma unroll
    for (int r = 0; r < 4; r++) {
        int n = n0 + ty + r*8, k = k0 + tx;
        float v = t[tx][ty + r*8];
        __nv_bfloat16 h = __float2bfloat16_rn(v);
        __nv_bfloat16 l = __float2bfloat16_rn(v - __bfloat162float(h));
        th[(size_t)n * DIMc + k] = h;
        tl[(size_t)n * DIMc + k] = l;
    }
}

__global__ void init_kmax_kernel() { g_kmax[threadIdx.x] = -FLT_MAX; }

// ==================== GEMM core, 2-A-pass structure ====================
// Phase 0 (it 0..15):  stage holds {Ah, Bh, Bl}; MMA Ah*Bh and Ah*Bl.
// Phase 1 (it 16..31): stage holds {Al, Bh};     MMA Al*Bh.
// CTA tile 128x128, BK=64, 8 warps (2M x 4N), warp tile 64x32.
// 2-stage double buffer, 48KB/stage -> 96KB dynamic smem, 2 CTAs/SM.
#define STAGE_BYTES 49152
#define GEMM_SMEM_BYTES (2 * STAGE_BYTES)
#define NIT 32

// ---- fused QKV GEMM with feature-map epilogue ----
__global__ __launch_bounds__(256)
void gemm_qkv_kernel(const __nv_bfloat16* __restrict__ Ahp, const __nv_bfloat16* __restrict__ Alp,
                     const __nv_bfloat16* __restrict__ wth, const __nv_bfloat16* __restrict__ wtl,
                     const float* __restrict__ bq, const float* __restrict__ bk,
                     const float* __restrict__ bv,
                     const unsigned char* __restrict__ mask,
                     const float* __restrict__ proj,
                     float* __restrict__ Vout)
{
    extern __shared__ __align__(1024) char smem[];
    const uint32_t sb = smem_u32(smem);
    const int tid = threadIdx.x, wid = tid >> 5, lane = tid & 31;
    const int wm = wid & 1, wn = wid >> 1;

    const int widx = blockIdx.x >> 3, nb = blockIdx.x & 7;
    const size_t WSZ = (size_t)DIMc * DIMc;
    const __nv_bfloat16* Bhw = wth + widx * WSZ;
    const __nv_bfloat16* Blw = wtl + widx * WSZ;
    const float* bias = (widx == 0) ? bq : ((widx == 1) ? bk : bv);

    const int arow0 = blockIdx.y * 128;
    const int brow0 = nb * 128;

    float acc[4][4][4];
#pragma unroll
    for (int i = 0; i < 4; i++)
#pragma unroll
        for (int j = 0; j < 4; j++)
#pragma unroll
            for (int v = 0; v < 4; v++) acc[i][j][v] = 0.f;

    int lrow[4], lc[4];
    uint32_t lsw[4];
#pragma unroll
    for (int i = 0; i < 4; i++) {
        int q = tid + i * 256;
        lrow[i] = q >> 3; lc[i] = q & 7;
        lsw[i] = (uint32_t)(lrow[i] * 128 + ((lc[i] ^ (lrow[i] & 7)) << 4));
    }

    auto load_stage = [&](int it, int buf) {
        const int phase = it >> 4, kt = it & 15, k0 = kt * 64;
        const __nv_bfloat16* Ag = ((phase == 0) ? Ahp : Alp) + (size_t)arow0 * DIMc + k0;
        const __nv_bfloat16* Bg = Bhw + (size_t)brow0 * DIMc + k0;
        uint32_t aS = sb + buf * STAGE_BYTES;
        uint32_t bS = aS + 16384;
#pragma unroll
        for (int i = 0; i < 4; i++) {
            cp_async16_ca(aS + lsw[i], Ag + (size_t)lrow[i] * DIMc + lc[i] * 8);
            cp_async16_cg(bS + lsw[i], Bg + (size_t)lrow[i] * DIMc + lc[i] * 8);
        }
        if (phase == 0) {
            const __nv_bfloat16* Bg2 = Blw + (size_t)brow0 * DIMc + k0;
            uint32_t b2S = aS + 32768;
#pragma unroll
            for (int i = 0; i < 4; i++)
                cp_async16_cg(b2S + lsw[i], Bg2 + (size_t)lrow[i] * DIMc + lc[i] * 8);
        }
        cp_commit();
    };

    const int a_r = wm * 64 + (lane & 7) + ((lane >> 3) & 1) * 8;
    const int a_cx = (lane >> 4);
    const int b_r = wn * 32 + ((lane >> 4) << 3) + (lane & 7);
    const int b_cx = (lane >> 3) & 1;

    load_stage(0, 0);

    for (int it = 0; it < NIT; ++it) {
        if (it + 1 < NIT) load_stage(it + 1, (it + 1) & 1);
        else cp_commit();
        cp_wait1();
        __syncthreads();

        const uint32_t aS = sb + (it & 1) * STAGE_BYTES;
        const int phase = it >> 4;

#pragma unroll
        for (int kk = 0; kk < 4; ++kk) {
            const int c0 = kk * 2;
            uint32_t af[4][4], bf[4][2];
#pragma unroll
            for (int mt = 0; mt < 4; ++mt) {
                int row = a_r + mt * 16;
                int ch = c0 + a_cx;
                ldmatrix_x4(af[mt], aS + (uint32_t)(row * 128 + ((ch ^ (row & 7)) << 4)));
            }
            // half 0: Bh
            {
                const uint32_t bS = aS + 16384;
#pragma unroll
                for (int ntp = 0; ntp < 2; ++ntp) {
                    int row = b_r + ntp * 16;
                    int ch = c0 + b_cx;
                    uint32_t r4[4];
                    ldmatrix_x4(r4, bS + (uint32_t)(row * 128 + ((ch ^ (row & 7)) << 4)));
                    bf[2*ntp][0] = r4[0]; bf[2*ntp][1] = r4[1];
                    bf[2*ntp+1][0] = r4[2]; bf[2*ntp+1][1] = r4[3];
                }
#pragma unroll
                for (int mt = 0; mt < 4; ++mt)
#pragma unroll
                    for (int nt = 0; nt < 4; ++nt)
                        mma16816(acc[mt][nt], af[mt], bf[nt]);
            }
            // half 1: Bl (phase 0 only), reuses bf registers
            if (phase == 0) {
                const uint32_t bS = aS + 32768;
#pragma unroll
                for (int ntp = 0; ntp < 2; ++ntp) {
                    int row = b_r + ntp * 16;
                    int ch = c0 + b_cx;
                    uint32_t r4[4];
                    ldmatrix_x4(r4, bS + (uint32_t)(row * 128 + ((ch ^ (row & 7)) << 4)));
                    bf[2*ntp][0] = r4[0]; bf[2*ntp][1] = r4[1];
                    bf[2*ntp+1][0] = r4[2]; bf[2*ntp+1][1] = r4[3];
                }
#pragma unroll
                for (int mt = 0; mt < 4; ++mt)
#pragma unroll
                    for (int nt = 0; nt < 4; ++nt)
                        mma16816(acc[mt][nt], af[mt], bf[nt]);
            }
        }
        __syncthreads();
    }

    const int gid = lane >> 2, tig = lane & 3;

    if (widx == 2) {
        // ---- V epilogue ----
#pragma unroll
        for (int mt = 0; mt < 4; ++mt) {
            int r0 = arow0 + wm * 64 + mt * 16 + gid;
            int r1 = r0 + 8;
            bool z0 = mask[r0] != 0, z1 = mask[r1] != 0;
#pragma unroll
            for (int nt = 0; nt < 4; ++nt) {
                int col = brow0 + wn * 32 + nt * 8 + tig * 2;
                float b0 = bias[col], b1 = bias[col + 1];
                float2 o0, o1;
                o0.x = z0 ? 0.f : acc[mt][nt][0] + b0;
                o0.y = z0 ? 0.f : acc[mt][nt][1] + b1;
                o1.x = z1 ? 0.f : acc[mt][nt][2] + b0;
                o1.y = z1 ? 0.f : acc[mt][nt][3] + b1;
                *(float2*)&Vout[(size_t)r0 * DIMc + col] = o0;
                *(float2*)&Vout[(size_t)r1 * DIMc + col] = o1;
            }
        }
        return;
    }

    // ---- Q/K epilogue: stage C in smem, compute feature maps ----
    float* Ct = (float*)smem;                           // [128][132]
    float* projS = (float*)(smem + 128 * 132 * 4);      // [32][65]
    __shared__ float wsmax[8][2];

#pragma unroll
    for (int mt = 0; mt < 4; ++mt) {
        int rr0 = wm * 64 + mt * 16 + gid;
        int rr1 = rr0 + 8;
#pragma unroll
        for (int nt = 0; nt < 4; ++nt) {
            int colL = wn * 32 + nt * 8 + tig * 2;
            float b0 = bias[brow0 + colL], b1 = bias[brow0 + colL + 1];
            Ct[rr0 * 132 + colL]     = acc[mt][nt][0] + b0;
            Ct[rr0 * 132 + colL + 1] = acc[mt][nt][1] + b1;
            Ct[rr1 * 132 + colL]     = acc[mt][nt][2] + b0;
            Ct[rr1 * 132 + colL + 1] = acc[mt][nt][3] + b1;
        }
    }
    for (int i = tid; i < Mm * DHh; i += 256)
        projS[(i >> 6) * 65 + (i & 63)] = proj[i];
    __syncthreads();

    float lmax0 = -FLT_MAX, lmax1 = -FLT_MAX;

    for (int i = 0; i < 32; ++i) {
        const int rh = wid * 32 + i;
        const int row = rh >> 1, hl = rh & 1;
        const float* crow = &Ct[row * 132 + hl * 64];

        float q0 = crow[lane], q1 = crow[lane + 32];
        float ss = q0 * q0 + q1 * q1;
#pragma unroll
        for (int o = 16; o > 0; o >>= 1) ss += __shfl_xor_sync(0xffffffffu, ss, o);
        float diag = DIAGC * ss;

        float dd = 0.f;
        const float* pr = &projS[lane * 65];
#pragma unroll
        for (int d = 0; d < DHh; d++) dd = fmaf(crow[d], pr[d], dd);
        dd *= NORMALIZER;

        const int gr = arow0 + row;
        const int b = gr >> 12, n = gr & (Nn - 1);
        const int h = nb * 2 + hl;
        const size_t outi = (((size_t)(b * Hh + h)) * Nn + n) * Mm + lane;

        if (widx == 0) {
            float mx = dd;
#pragma unroll
            for (int o = 16; o > 0; o >>= 1) mx = fmaxf(mx, __shfl_xor_sync(0xffffffffu, mx, o));
            g_qf[outi] = RATIO * (__expf(dd - diag - mx) + FEPS);
        } else {
            g_kf[outi] = dd - diag;
            if (hl == 0) lmax0 = fmaxf(lmax0, dd); else lmax1 = fmaxf(lmax1, dd);
        }
    }

    if (widx == 1) {
#pragma unroll
        for (int o = 16; o > 0; o >>= 1) {
            lmax0 = fmaxf(lmax0, __shfl_xor_sync(0xffffffffu, lmax0, o));
            lmax1 = fmaxf(lmax1, __shfl_xor_sync(0xffffffffu, lmax1, o));
        }
        if (lane == 0) { wsmax[wid][0] = lmax0; wsmax[wid][1] = lmax1; }
        __syncthreads();
        if (tid < 2) {
            float m = wsmax[0][tid];
#pragma unroll
            for (int w = 1; w < 8; w++) m = fmaxf(m, wsmax[w][tid]);
            const int b = (arow0 >> 12);
            atomic_fmax(&g_kmax[b * Hh + nb * 2 + tid], m);
        }
    }
}

// ---- plain GEMM for output projection (same 2-phase mainloop) ----
__global__ __launch_bounds__(256)
void gemm_o_kernel(const __nv_bfloat16* __restrict__ Ahp, const __nv_bfloat16* __restrict__ Alp,
                   const __nv_bfloat16* __restrict__ Bhw, const __nv_bfloat16* __restrict__ Blw,
                   const float* __restrict__ bias, float* __restrict__ C)
{
    extern __shared__ __align__(1024) char smem[];
    const uint32_t sb = smem_u32(smem);
    const int tid = threadIdx.x, wid = tid >> 5, lane = tid & 31;
    const int wm = wid & 1, wn = wid >> 1;

    const int arow0 = blockIdx.y * 128;
    const int brow0 = blockIdx.x * 128;

    float acc[4][4][4];
#pragma unroll
    for (int i = 0; i < 4; i++)
#pragma unroll
        for (int j = 0; j < 4; j++)
#pragma unroll
            for (int v = 0; v < 4; v++) acc[i][j][v] = 0.f;

    int lrow[4], lc[4];
    uint32_t lsw[4];
#pragma unroll
    for (int i = 0; i < 4; i++) {
        int q = tid + i * 256;
        lrow[i] = q >> 3; lc[i] = q & 7;
        lsw[i] = (uint32_t)(lrow[i] * 128 + ((lc[i] ^ (lrow[i] & 7)) << 4));
    }

    auto load_stage = [&](int it, int buf) {
        const int phase = it >> 4, kt = it & 15, k0 = kt * 64;
        const __nv_bfloat16* Ag = ((phase == 0) ? Ahp : Alp) + (size_t)arow0 * DIMc + k0;
        const __nv_bfloat16* Bg = Bhw + (size_t)brow0 * DIMc + k0;
        uint32_t aS = sb + buf * STAGE_BYTES;
        uint32_t bS = aS + 16384;
#pragma unroll
        for (int i = 0; i < 4; i++) {
            cp_async16_ca(aS + lsw[i], Ag + (size_t)lrow[i] * DIMc + lc[i] * 8);
            cp_async16_cg(bS + lsw[i], Bg + (size_t)lrow[i] * DIMc + lc[i] * 8);
        }
        if (phase == 0) {
            const __nv_bfloat16* Bg2 = Blw + (size_t)brow0 * DIMc + k0;
            uint32_t b2S = aS + 32768;
#pragma unroll
            for (int i = 0; i < 4; i++)
                cp_async16_cg(b2S + lsw[i], Bg2 + (size_t)lrow[i] * DIMc + lc[i] * 8);
        }
        cp_commit();
    };

    const int a_r = wm * 64 + (lane & 7) + ((lane >> 3) & 1) * 8;
    const int a_cx = (lane >> 4);
    const int b_r = wn * 32 + ((lane >> 4) << 3) + (lane & 7);
    const int b_cx = (lane >> 3) & 1;

    load_stage(0, 0);

    for (int it = 0; it < NIT; ++it) {
        if (it + 1 < NIT) load_stage(it + 1, (it + 1) & 1);
        else cp_commit();
        cp_wait1();
        __syncthreads();

        const uint32_t aS = sb + (it & 1) * STAGE_BYTES;
        const int phase = it >> 4;

#pragma unroll
        for (int kk = 0; kk < 4; ++kk) {
            const int c0 = kk * 2;
            uint32_t af[4][4], bf[4][2];
#pragma unroll
            for (int mt = 0; mt < 4; ++mt) {
                int row = a_r + mt * 16;
                int ch = c0 + a_cx;
                ldmatrix_x4(af[mt], aS + (uint32_t)(row * 128 + ((ch ^ (row & 7)) << 4)));
            }
            {
                const uint32_t bS = aS + 16384;
#pragma unroll
                for (int ntp = 0; ntp < 2; ++ntp) {
                    int row = b_r + ntp * 16;
                    int ch = c0 + b_cx;
                    uint32_t r4[4];
                    ldmatrix_x4(r4, bS + (uint32_t)(row * 128 + ((ch ^ (row & 7)) << 4)));
                    bf[2*ntp][0] = r4[0]; bf[2*ntp][1] = r4[1];
                    bf[2*ntp+1][0] = r4[2]; bf[2*ntp+1][1] = r4[3];
                }
#pragma unroll
                for (int mt = 0; mt < 4; ++mt)
#pragma unroll
                    for (int nt = 0; nt < 4; ++nt)
                        mma16816(acc[mt][nt], af[mt], bf[nt]);
            }
            if (phase == 0) {
                const uint32_t bS = aS + 32768;
#pragma unroll
                for (int ntp = 0; ntp < 2; ++ntp) {
                    int row = b_r + ntp * 16;
                    int ch = c0 + b_cx;
                    uint32_t r4[4];
                    ldmatrix_x4(r4, bS + (uint32_t)(row * 128 + ((ch ^ (row & 7)) << 4)));
                    bf[2*ntp][0] = r4[0]; bf[2*ntp][1] = r4[1];
                    bf[2*ntp+1][0] = r4[2]; bf[2*ntp+1][1] = r4[3];
                }
#pragma unroll
                for (int mt = 0; mt < 4; ++mt)
#pragma unroll
                    for (int nt = 0; nt < 4; ++nt)
                        mma16816(acc[mt][nt], af[mt], bf[nt]);
            }
        }
        __syncthreads();
    }

    const int gid = lane >> 2, tig = lane & 3;
#pragma unroll
    for (int mt = 0; mt < 4; ++mt) {
        int r0 = arow0 + wm * 64 + mt * 16 + gid;
        int r1 = r0 + 8;
#pragma unroll
        for (int nt = 0; nt < 4; ++nt) {
            int col = brow0 + wn * 32 + nt * 8 + tig * 2;
            float b0 = bias[col], b1 = bias[col + 1];
            float2 o0, o1;
            o0.x = acc[mt][nt][0] + b0;
            o0.y = acc[mt][nt][1] + b1;
            o1.x = acc[mt][nt][2] + b0;
            o1.y = acc[mt][nt][3] + b1;
            *(float2*)&C[(size_t)r0 * DIMc + col] = o0;
            *(float2*)&C[(size_t)r1 * DIMc + col] = o1;
        }
    }
}

// ==================== attention kernels ====================
// kcs: sum over n of exp-mapped kf (exp applied on the fly)
__global__ __launch_bounds__(256)
void kcs_kernel()
{
    const int bh = blockIdx.x;
    const int t = threadIdx.x;
    const int m = t & 31, g = t >> 5;
    const float kmax = g_kmax[bh];
    const float* base = g_kf + (size_t)bh * (Nn * Mm);
    float s = 0.f;
    for (int n = g; n < Nn; n += 8)
        s += RATIO * (__expf(base[(size_t)n * Mm + m] - kmax) + FEPS);
    __shared__ float sm[8][32];
    sm[g][m] = s;
    __syncthreads();
    if (g == 0) {
        float tot = 0.f;
#pragma unroll
        for (int i = 0; i < 8; i++) tot += sm[i][m];
        g_kcs[bh * Mm + m] = tot;
    }
}

// context = kf^T @ v per (b,h), exp applied at smem load, NSEG n-segments
__global__ __launch_bounds__(256)
void context_part_kernel()
{
    const int bh = blockIdx.x, seg = blockIdx.y;
    const int b = bh >> 4, h = bh & 15;
    const int t = threadIdx.x;
    const int e = t & 63, mg = t >> 6;

    __shared__ float kfS[32][33];
    __shared__ float vS[32][DHh];

    const float kmax = g_kmax[bh];

    float acc[8];
#pragma unroll
    for (int i = 0; i < 8; i++) acc[i] = 0.f;

    const float* kfb = g_kf + (size_t)bh * (Nn * Mm);
    const float* vb  = g_v  + (size_t)b * Nn * DIMc + h * DHh;
    const int nbeg = seg * (Nn / NSEG);

    for (int n0 = nbeg; n0 < nbeg + Nn / NSEG; n0 += 32) {
        for (int i = t; i < 32 * 32; i += 256) {
            float raw = kfb[(size_t)(n0 + (i >> 5)) * Mm + (i & 31)];
            kfS[i >> 5][i & 31] = RATIO * (__expf(raw - kmax) + FEPS);
        }
        for (int i = t; i < 32 * 64; i += 256)
            vS[i >> 6][i & 63] = vb[(size_t)(n0 + (i >> 6)) * DIMc + (i & 63)];
        __syncthreads();
#pragma unroll
        for (int nn = 0; nn < 32; nn++) {
            float vv = vS[nn][e];
#pragma unroll
            for (int i = 0; i < 8; i++)
                acc[i] = fmaf(kfS[nn][mg + 4 * i], vv, acc[i]);
        }
        __syncthreads();
    }
#pragma unroll
    for (int i = 0; i < 8; i++)
        g_ctxp[((size_t)bh * NSEG + seg) * (Mm * DHh) + (mg + 4 * i) * DHh + e] = acc[i];
}

__global__ __launch_bounds__(256)
void ctx_reduce_kernel()
{
    const int bh = blockIdx.x;
    for (int i = threadIdx.x; i < Mm * DHh; i += 256) {
        float s = 0.f;
#pragma unroll
        for (int g = 0; g < NSEG; g++)
            s += g_ctxp[((size_t)bh * NSEG + g) * (Mm * DHh) + i];
        g_ctx[(size_t)bh * (Mm * DHh) + i] = s;
    }
}

__global__ __launch_bounds__(256)
void attn_out_kernel(__nv_bfloat16* __restrict__ oh, __nv_bfloat16* __restrict__ ol)
{
    __shared__ float ctxS[Mm][DHh];
    __shared__ float kcsS[Mm];

    const int tid = threadIdx.x;
    const int warp = tid >> 5, lane = tid & 31;
    const int r = blockIdx.x * 8 + warp;
    const int bh = r >> 12;
    const int n  = r & (Nn - 1);
    const int b  = bh >> 4, h = bh & 15;

    for (int i = tid; i < Mm * DHh; i += 256)
        ctxS[i >> 6][i & 63] = g_ctx[(size_t)bh * (Mm * DHh) + i];
    if (tid < Mm) kcsS[tid] = g_kcs[bh * Mm + tid];
    __syncthreads();

    float myqf = g_qf[(size_t)r * Mm + lane];
    float D = myqf * kcsS[lane];
#pragma unroll
    for (int o = 16; o > 0; o >>= 1) D += __shfl_xor_sync(0xffffffffu, D, o);
    float Dinv = 1.0f / D;

    float o0 = 0.f, o1 = 0.f;
#pragma unroll
    for (int m = 0; m < Mm; m++) {
        float qv = __shfl_sync(0xffffffffu, myqf, m);
        o0 = fmaf(qv, ctxS[m][lane], o0);
        o1 = fmaf(qv, ctxS[m][lane + 32], o1);
    }
    o0 *= Dinv; o1 *= Dinv;

    size_t base = (size_t)(b * Nn + n) * DIMc + h * DHh;
    __nv_bfloat16 h0 = __float2bfloat16_rn(o0);
    __nv_bfloat16 h1 = __float2bfloat16_rn(o1);
    oh[base + lane]      = h0;
    oh[base + lane + 32] = h1;
    ol[base + lane]      = __float2bfloat16_rn(o0 - __bfloat162float(h0));
    ol[base + lane + 32] = __float2bfloat16_rn(o1 - __bfloat162float(h1));
}

// ==================== launch ====================
extern "C" void kernel_launch(void* const* d_in, const int* in_sizes, int n_in,
                              void* d_out, int out_size)
{
    const float*         x    = (const float*)d_in[0];
    const unsigned char* mask = (const unsigned char*)d_in[1];
    const float*         proj = (const float*)d_in[2];
    const float* Wq = (const float*)d_in[3];
    const float* bq = (const float*)d_in[4];
    const float* Wk = (const float*)d_in[5];
    const float* bk = (const float*)d_in[6];
    const float* Wv = (const float*)d_in[7];
    const float* bv = (const float*)d_in[8];
    const float* Wo = (const float*)d_in[9];
    const float* bo = (const float*)d_in[10];
    float* out = (float*)d_out;

    float *v_;
    __nv_bfloat16 *xh_, *xl_, *wth_, *wtl_;
    cudaGetSymbolAddress((void**)&v_,   g_v);
    cudaGetSymbolAddress((void**)&xh_,  g_xh);
    cudaGetSymbolAddress((void**)&xl_,  g_xl);
    cudaGetSymbolAddress((void**)&wth_, g_wth);
    cudaGetSymbolAddress((void**)&wtl_, g_wtl);

    cudaFuncSetAttribute(gemm_qkv_kernel,
                         cudaFuncAttributeMaxDynamicSharedMemorySize, GEMM_SMEM_BYTES);
    cudaFuncSetAttribute(gemm_o_kernel,
                         cudaFuncAttributeMaxDynamicSharedMemorySize, GEMM_SMEM_BYTES);

    const size_t WSZ = (size_t)DIMc * DIMc;
    const int nElem = Bz * Nn * DIMc;
    dim3 gSplitT(32, 32);

    split_kernel<<<nElem / (256 * 4), 256>>>((const float4*)x,
        (__nv_bfloat162*)xh_, (__nv_bfloat162*)xl_);
    splitT_kernel<<<gSplitT, 256>>>(Wq, wth_ + 0*WSZ, wtl_ + 0*WSZ);
    splitT_kernel<<<gSplitT, 256>>>(Wk, wth_ + 1*WSZ, wtl_ + 1*WSZ);
    splitT_kernel<<<gSplitT, 256>>>(Wv, wth_ + 2*WSZ, wtl_ + 2*WSZ);
    splitT_kernel<<<gSplitT, 256>>>(Wo, wth_ + 3*WSZ, wtl_ + 3*WSZ);
    init_kmax_kernel<<<1, Bz * Hh>>>();

    gemm_qkv_kernel<<<dim3(24, 128), 256, GEMM_SMEM_BYTES>>>(
        xh_, xl_, wth_, wtl_, bq, bk, bv, mask, proj, v_);

    kcs_kernel<<<Bz * Hh, 256>>>();
    context_part_kernel<<<dim3(Bz * Hh, NSEG), 256>>>();
    ctx_reduce_kernel<<<Bz * Hh, 256>>>();
    attn_out_kernel<<<(Bz * Hh * Nn) / 8, 256>>>(xh_, xl_);

    gemm_o_kernel<<<dim3(8, 128), 256, GEMM_SMEM_BYTES>>>(
        xh_, xl_, wth_ + 3*WSZ, wtl_ + 3*WSZ, bo, out);
}

// round 17
// speedup vs baseline: 1.0691x; 1.0691x over previous
#include <cuda_runtime.h>
#include <cuda_bf16.h>
#include <math.h>
#include <float.h>
#include <stdint.h>

// Problem constants
#define Bz   4
#define Nn   4096
#define DIMc 1024
#define Hh   16
#define DHh  64
#define Mm   32

#define NORMALIZER 0.3535533905932738f   // 64^-0.25
#define DIAGC      0.0625f               // 0.5 * 64^-0.5
#define RATIO      0.17677669529663687f  // 32^-0.5
#define FEPS       1e-4f

#define NSEG 16

// ---------------- scratch (device globals) -------------
__device__ float g_v   [Bz*Nn*DIMc];
__device__ float g_qf  [Bz*Hh*Nn*Mm];
__device__ float g_kf  [Bz*Hh*Nn*Mm];     // raw dd - diag (exp applied at use)
__device__ float g_kmax[Bz*Hh];
__device__ float g_kcs [Bz*Hh*Mm];
__device__ float g_kcsp[Bz*Hh*NSEG*Mm];
__device__ float g_ctx [Bz*Hh*Mm*DHh];
__device__ float g_ctxp[Bz*Hh*NSEG*Mm*DHh];

__device__ __nv_bfloat16 g_xh [Bz*Nn*DIMc];
__device__ __nv_bfloat16 g_xl [Bz*Nn*DIMc];
__device__ __nv_bfloat16 g_wth[4*DIMc*DIMc];
__device__ __nv_bfloat16 g_wtl[4*DIMc*DIMc];

// ==================== helpers ====================
__device__ __forceinline__ uint32_t smem_u32(const void* p) {
    uint32_t a;
    asm("{ .reg .u64 t; cvta.to.shared.u64 t, %1; cvt.u32.u64 %0, t; }" : "=r"(a) : "l"(p));
    return a;
}
__device__ __forceinline__ void cp_async16(uint32_t saddr, const void* gaddr) {
    asm volatile("cp.async.cg.shared.global [%0], [%1], 16;" :: "r"(saddr), "l"(gaddr));
}
__device__ __forceinline__ void cp_commit() {
    asm volatile("cp.async.commit_group;" ::: "memory");
}
__device__ __forceinline__ void cp_wait2() {
    asm volatile("cp.async.wait_group 2;" ::: "memory");
}
__device__ __forceinline__ void ldmatrix_x4(uint32_t* r, uint32_t addr) {
    asm volatile("ldmatrix.sync.aligned.m8n8.x4.shared.b16 {%0,%1,%2,%3}, [%4];"
                 : "=r"(r[0]), "=r"(r[1]), "=r"(r[2]), "=r"(r[3]) : "r"(addr));
}
__device__ __forceinline__ void mma16816(float* d, const uint32_t* a, const uint32_t* b) {
    asm volatile(
        "mma.sync.aligned.m16n8k16.row.col.f32.bf16.bf16.f32 "
        "{%0,%1,%2,%3}, {%4,%5,%6,%7}, {%8,%9}, {%0,%1,%2,%3};"
        : "+f"(d[0]), "+f"(d[1]), "+f"(d[2]), "+f"(d[3])
        : "r"(a[0]), "r"(a[1]), "r"(a[2]), "r"(a[3]), "r"(b[0]), "r"(b[1]));
}
__device__ __forceinline__ void atomic_fmax(float* addr, float m) {
    int* ia = (int*)addr;
    int old = *ia;
    while (__int_as_float(old) < m) {
        int assumed = old;
        old = atomicCAS(ia, assumed, __float_as_int(m));
        if (old == assumed) break;
    }
}

// ==================== split conversion kernels ====================
__global__ __launch_bounds__(256)
void split_kernel(const float4* __restrict__ in,
                  __nv_bfloat162* __restrict__ hi, __nv_bfloat162* __restrict__ lo)
{
    int i = blockIdx.x * 256 + threadIdx.x;
    float4 v = in[i];
    __nv_bfloat162 h0, h1, l0, l1;
    h0.x = __float2bfloat16_rn(v.x); l0.x = __float2bfloat16_rn(v.x - __bfloat162float(h0.x));
    h0.y = __float2bfloat16_rn(v.y); l0.y = __float2bfloat16_rn(v.y - __bfloat162float(h0.y));
    h1.x = __float2bfloat16_rn(v.z); l1.x = __float2bfloat16_rn(v.z - __bfloat162float(h1.x));
    h1.y = __float2bfloat16_rn(v.w); l1.y = __float2bfloat16_rn(v.w - __bfloat162float(h1.y));
    hi[2*i] = h0; hi[2*i+1] = h1;
    lo[2*i] = l0; lo[2*i+1] = l1;
}

__global__ __launch_bounds__(256)
void splitT_kernel(const float* __restrict__ W,
                   __nv_bfloat16* __restrict__ th, __nv_bfloat16* __restrict__ tl)
{
    __shared__ float t[32][33];
    int tx = threadIdx.x & 31, ty = threadIdx.x >> 5;
    int k0 = blockIdx.y * 32, n0 = blockIdx.x * 32;
#pragma unroll
    for (int r = 0; r < 4; r++)
        t[ty + r*8][tx] = W[(size_t)(k0 + ty + r*8) * DIMc + n0 + tx];
    __syncthreads();
#pragma unroll
    for (int r = 0; r < 4; r++) {
        int n = n0 + ty + r*8, k = k0 + tx;
        float v = t[tx][ty + r*8];
        __nv_bfloat16 h = __float2bfloat16_rn(v);
        __nv_bfloat16 l = __float2bfloat16_rn(v - __bfloat162float(h));
        th[(size_t)n * DIMc + k] = h;
        tl[(size_t)n * DIMc + k] = l;
    }
}

__global__ void init_kmax_kernel() { g_kmax[threadIdx.x] = -FLT_MAX; }

// ==================== GEMM core (R15-proven: 3-pass, 3-stage) ====================
// CTA tile 128x128, BK=64, 8 warps (2M x 4N), warp tile 64x32.
#define GEMM_SMEM_BYTES (3 * 32768)
#define NIT 48   // 3 passes * 16 k-tiles

// ---- fused QKV GEMM with feature-map epilogue ----
// grid: (24, 128). bx -> widx = bx>>3 in {0:Q, 1:K, 2:V}, nb = bx&7.
__global__ __launch_bounds__(256)
void gemm_qkv_kernel(const __nv_bfloat16* __restrict__ Ahp, const __nv_bfloat16* __restrict__ Alp,
                     const __nv_bfloat16* __restrict__ wth, const __nv_bfloat16* __restrict__ wtl,
                     const float* __restrict__ bq, const float* __restrict__ bk,
                     const float* __restrict__ bv,
                     const unsigned char* __restrict__ mask,
                     const float* __restrict__ proj,
                     float* __restrict__ Vout)
{
    extern __shared__ __align__(1024) char smem[];
    const uint32_t sb = smem_u32(smem);
    const int tid = threadIdx.x, wid = tid >> 5, lane = tid & 31;
    const int wm = wid & 1, wn = wid >> 1;

    const int widx = blockIdx.x >> 3, nb = blockIdx.x & 7;
    const size_t WSZ = (size_t)DIMc * DIMc;
    const __nv_bfloat16* Bh = wth + widx * WSZ;
    const __nv_bfloat16* Bl = wtl + widx * WSZ;
    const float* bias = (widx == 0) ? bq : ((widx == 1) ? bk : bv);

    const int arow0 = blockIdx.y * 128;
    const int brow0 = nb * 128;

    float acc[4][4][4];
#pragma unroll
    for (int i = 0; i < 4; i++)
#pragma unroll
        for (int j = 0; j < 4; j++)
#pragma unroll
            for (int v = 0; v < 4; v++) acc[i][j][v] = 0.f;

    int lrow[4], lc[4];
    uint32_t lsw[4];
#pragma unroll
    for (int i = 0; i < 4; i++) {
        int q = tid + i * 256;
        lrow[i] = q >> 3; lc[i] = q & 7;
        lsw[i] = (uint32_t)(lrow[i] * 128 + ((lc[i] ^ (lrow[i] & 7)) << 4));
    }

    auto load_stage = [&](int it, int stage) {
        const int p = it >> 4, kt = it & 15, k0 = kt * 64;
        const __nv_bfloat16* Asrc = (p == 1) ? Alp : Ahp;
        const __nv_bfloat16* Bsrc = (p == 2) ? Bl : Bh;
        const __nv_bfloat16* Ag = Asrc + (size_t)arow0 * DIMc + k0;
        const __nv_bfloat16* Bg = Bsrc + (size_t)brow0 * DIMc + k0;
        uint32_t aS = sb + stage * 32768;
        uint32_t bS = aS + 16384;
#pragma unroll
        for (int i = 0; i < 4; i++) {
            cp_async16(aS + lsw[i], Ag + (size_t)lrow[i] * DIMc + lc[i] * 8);
            cp_async16(bS + lsw[i], Bg + (size_t)lrow[i] * DIMc + lc[i] * 8);
        }
        cp_commit();
    };

    const int a_r = wm * 64 + (lane & 7) + ((lane >> 3) & 1) * 8;
    const int a_cx = (lane >> 4);
    const int b_r = wn * 32 + ((lane >> 4) << 3) + (lane & 7);
    const int b_cx = (lane >> 3) & 1;

    load_stage(0, 0);
    load_stage(1, 1);

    for (int it = 0; it < NIT; ++it) {
        if (it + 2 < NIT) load_stage(it + 2, (it + 2) % 3);
        else cp_commit();
        cp_wait2();
        __syncthreads();

        const int stage = it % 3;
        const uint32_t aS = sb + stage * 32768;
        const uint32_t bS = aS + 16384;

#pragma unroll
        for (int kk = 0; kk < 4; ++kk) {
            const int c0 = kk * 2;
            uint32_t af[4][4], bf[4][2];
#pragma unroll
            for (int mt = 0; mt < 4; ++mt) {
                int row = a_r + mt * 16;
                int ch = c0 + a_cx;
                ldmatrix_x4(af[mt], aS + (uint32_t)(row * 128 + ((ch ^ (row & 7)) << 4)));
            }
#pragma unroll
            for (int ntp = 0; ntp < 2; ++ntp) {
                int row = b_r + ntp * 16;
                int ch = c0 + b_cx;
                uint32_t r4[4];
                ldmatrix_x4(r4, bS + (uint32_t)(row * 128 + ((ch ^ (row & 7)) << 4)));
                bf[2*ntp][0] = r4[0]; bf[2*ntp][1] = r4[1];
                bf[2*ntp+1][0] = r4[2]; bf[2*ntp+1][1] = r4[3];
            }
#pragma unroll
            for (int mt = 0; mt < 4; ++mt)
#pragma unroll
                for (int nt = 0; nt < 4; ++nt)
                    mma16816(acc[mt][nt], af[mt], bf[nt]);
        }
        __syncthreads();
    }

    const int gid = lane >> 2, tig = lane & 3;

    if (widx == 2) {
        // ---- V epilogue: bias + mask, direct write ----
#pragma unroll
        for (int mt = 0; mt < 4; ++mt) {
            int r0 = arow0 + wm * 64 + mt * 16 + gid;
            int r1 = r0 + 8;
            bool z0 = mask[r0] != 0, z1 = mask[r1] != 0;
#pragma unroll
            for (int nt = 0; nt < 4; ++nt) {
                int col = brow0 + wn * 32 + nt * 8 + tig * 2;
                float b0 = bias[col], b1 = bias[col + 1];
                float2 o0, o1;
                o0.x = z0 ? 0.f : acc[mt][nt][0] + b0;
                o0.y = z0 ? 0.f : acc[mt][nt][1] + b1;
                o1.x = z1 ? 0.f : acc[mt][nt][2] + b0;
                o1.y = z1 ? 0.f : acc[mt][nt][3] + b1;
                *(float2*)&Vout[(size_t)r0 * DIMc + col] = o0;
                *(float2*)&Vout[(size_t)r1 * DIMc + col] = o1;
            }
        }
        return;
    }

    // ---- Q/K epilogue: stage C in smem, compute feature maps ----
    float* Ct = (float*)smem;                           // [128][132]
    float* projS = (float*)(smem + 128 * 132 * 4);      // [32][65]
    __shared__ float wsmax[8][2];

#pragma unroll
    for (int mt = 0; mt < 4; ++mt) {
        int rr0 = wm * 64 + mt * 16 + gid;
        int rr1 = rr0 + 8;
#pragma unroll
        for (int nt = 0; nt < 4; ++nt) {
            int colL = wn * 32 + nt * 8 + tig * 2;
            float b0 = bias[brow0 + colL], b1 = bias[brow0 + colL + 1];
            Ct[rr0 * 132 + colL]     = acc[mt][nt][0] + b0;
            Ct[rr0 * 132 + colL + 1] = acc[mt][nt][1] + b1;
            Ct[rr1 * 132 + colL]     = acc[mt][nt][2] + b0;
            Ct[rr1 * 132 + colL + 1] = acc[mt][nt][3] + b1;
        }
    }
    for (int i = tid; i < Mm * DHh; i += 256)
        projS[(i >> 6) * 65 + (i & 63)] = proj[i];
    __syncthreads();

    float lmax0 = -FLT_MAX, lmax1 = -FLT_MAX;

    for (int i = 0; i < 32; ++i) {
        const int rh = wid * 32 + i;
        const int row = rh >> 1, hl = rh & 1;
        const float* crow = &Ct[row * 132 + hl * 64];

        float q0 = crow[lane], q1 = crow[lane + 32];
        float ss = q0 * q0 + q1 * q1;
#pragma unroll
        for (int o = 16; o > 0; o >>= 1) ss += __shfl_xor_sync(0xffffffffu, ss, o);
        float diag = DIAGC * ss;

        float dd = 0.f;
        const float* pr = &projS[lane * 65];
#pragma unroll
        for (int d = 0; d < DHh; d++) dd = fmaf(crow[d], pr[d], dd);
        dd *= NORMALIZER;

        const int gr = arow0 + row;
        const int b = gr >> 12, n = gr & (Nn - 1);
        const int h = nb * 2 + hl;
        const size_t outi = (((size_t)(b * Hh + h)) * Nn + n) * Mm + lane;

        if (widx == 0) {
            float mx = dd;
#pragma unroll
            for (int o = 16; o > 0; o >>= 1) mx = fmaxf(mx, __shfl_xor_sync(0xffffffffu, mx, o));
            g_qf[outi] = RATIO * (__expf(dd - diag - mx) + FEPS);
        } else {
            g_kf[outi] = dd - diag;
            if (hl == 0) lmax0 = fmaxf(lmax0, dd); else lmax1 = fmaxf(lmax1, dd);
        }
    }

    if (widx == 1) {
#pragma unroll
        for (int o = 16; o > 0; o >>= 1) {
            lmax0 = fmaxf(lmax0, __shfl_xor_sync(0xffffffffu, lmax0, o));
            lmax1 = fmaxf(lmax1, __shfl_xor_sync(0xffffffffu, lmax1, o));
        }
        if (lane == 0) { wsmax[wid][0] = lmax0; wsmax[wid][1] = lmax1; }
        __syncthreads();
        if (tid < 2) {
            float m = wsmax[0][tid];
#pragma unroll
            for (int w = 1; w < 8; w++) m = fmaxf(m, wsmax[w][tid]);
            const int b = (arow0 >> 12);
            atomic_fmax(&g_kmax[b * Hh + nb * 2 + tid], m);
        }
    }
}

// ---- plain GEMM for output projection (R15 mainloop) ----
__global__ __launch_bounds__(256)
void gemm_o_kernel(const __nv_bfloat16* __restrict__ Ahp, const __nv_bfloat16* __restrict__ Alp,
                   const __nv_bfloat16* __restrict__ Bh, const __nv_bfloat16* __restrict__ Bl,
                   const float* __restrict__ bias, float* __restrict__ C)
{
    extern __shared__ __align__(1024) char smem[];
    const uint32_t sb = smem_u32(smem);
    const int tid = threadIdx.x, wid = tid >> 5, lane = tid & 31;
    const int wm = wid & 1, wn = wid >> 1;

    const int arow0 = blockIdx.y * 128;
    const int brow0 = blockIdx.x * 128;

    float acc[4][4][4];
#pragma unroll
    for (int i = 0; i < 4; i++)
#pragma unroll
        for (int j = 0; j < 4; j++)
#pragma unroll
            for (int v = 0; v < 4; v++) acc[i][j][v] = 0.f;

    int lrow[4], lc[4];
    uint32_t lsw[4];
#pragma unroll
    for (int i = 0; i < 4; i++) {
        int q = tid + i * 256;
        lrow[i] = q >> 3; lc[i] = q & 7;
        lsw[i] = (uint32_t)(lrow[i] * 128 + ((lc[i] ^ (lrow[i] & 7)) << 4));
    }

    auto load_stage = [&](int it, int stage) {
        const int p = it >> 4, kt = it & 15, k0 = kt * 64;
        const __nv_bfloat16* Asrc = (p == 1) ? Alp : Ahp;
        const __nv_bfloat16* Bsrc = (p == 2) ? Bl : Bh;
        const __nv_bfloat16* Ag = Asrc + (size_t)arow0 * DIMc + k0;
        const __nv_bfloat16* Bg = Bsrc + (size_t)brow0 * DIMc + k0;
        uint32_t aS = sb + stage * 32768;
        uint32_t bS = aS + 16384;
#pragma unroll
        for (int i = 0; i < 4; i++) {
            cp_async16(aS + lsw[i], Ag + (size_t)lrow[i] * DIMc + lc[i] * 8);
            cp_async16(bS + lsw[i], Bg + (size_t)lrow[i] * DIMc + lc[i] * 8);
        }
        cp_commit();
    };

    const int a_r = wm * 64 + (lane & 7) + ((lane >> 3) & 1) * 8;
    const int a_cx = (lane >> 4);
    const int b_r = wn * 32 + ((lane >> 4) << 3) + (lane & 7);
    const int b_cx = (lane >> 3) & 1;

    load_stage(0, 0);
    load_stage(1, 1);

    for (int it = 0; it < NIT; ++it) {
        if (it + 2 < NIT) load_stage(it + 2, (it + 2) % 3);
        else cp_commit();
        cp_wait2();
        __syncthreads();

        const int stage = it % 3;
        const uint32_t aS = sb + stage * 32768;
        const uint32_t bS = aS + 16384;

#pragma unroll
        for (int kk = 0; kk < 4; ++kk) {
            const int c0 = kk * 2;
            uint32_t af[4][4], bf[4][2];
#pragma unroll
            for (int mt = 0; mt < 4; ++mt) {
                int row = a_r + mt * 16;
                int ch = c0 + a_cx;
                ldmatrix_x4(af[mt], aS + (uint32_t)(row * 128 + ((ch ^ (row & 7)) << 4)));
            }
#pragma unroll
            for (int ntp = 0; ntp < 2; ++ntp) {
                int row = b_r + ntp * 16;
                int ch = c0 + b_cx;
                uint32_t r4[4];
                ldmatrix_x4(r4, bS + (uint32_t)(row * 128 + ((ch ^ (row & 7)) << 4)));
                bf[2*ntp][0] = r4[0]; bf[2*ntp][1] = r4[1];
                bf[2*ntp+1][0] = r4[2]; bf[2*ntp+1][1] = r4[3];
            }
#pragma unroll
            for (int mt = 0; mt < 4; ++mt)
#pragma unroll
                for (int nt = 0; nt < 4; ++nt)
                    mma16816(acc[mt][nt], af[mt], bf[nt]);
        }
        __syncthreads();
    }

    const int gid = lane >> 2, tig = lane & 3;
#pragma unroll
    for (int mt = 0; mt < 4; ++mt) {
        int r0 = arow0 + wm * 64 + mt * 16 + gid;
        int r1 = r0 + 8;
#pragma unroll
        for (int nt = 0; nt < 4; ++nt) {
            int col = brow0 + wn * 32 + nt * 8 + tig * 2;
            float b0 = bias[col], b1 = bias[col + 1];
            float2 o0, o1;
            o0.x = acc[mt][nt][0] + b0;
            o0.y = acc[mt][nt][1] + b1;
            o1.x = acc[mt][nt][2] + b0;
            o1.y = acc[mt][nt][3] + b1;
            *(float2*)&C[(size_t)r0 * DIMc + col] = o0;
            *(float2*)&C[(size_t)r1 * DIMc + col] = o1;
        }
    }
}

// ==================== attention kernels ====================
// context = kf^T @ v per (b,h) with exp applied at smem load; also accumulates
// the per-segment k_cumsum partials from the same smem tiles.
__global__ __launch_bounds__(256)
void context_part_kernel()
{
    const int bh = blockIdx.x, seg = blockIdx.y;
    const int b = bh >> 4, h = bh & 15;
    const int t = threadIdx.x;
    const int e = t & 63, mg = t >> 6;

    __shared__ float kfS[32][33];
    __shared__ float vS[32][DHh];

    const float kmax = g_kmax[bh];

    float acc[8];
#pragma unroll
    for (int i = 0; i < 8; i++) acc[i] = 0.f;
    float skcs = 0.f;   // meaningful for t < 32 only

    const float* kfb = g_kf + (size_t)bh * (Nn * Mm);
    const float* vb  = g_v  + (size_t)b * Nn * DIMc + h * DHh;
    const int nbeg = seg * (Nn / NSEG);

    for (int n0 = nbeg; n0 < nbeg + Nn / NSEG; n0 += 32) {
        for (int i = t; i < 32 * 32; i += 256) {
            float raw = kfb[(size_t)(n0 + (i >> 5)) * Mm + (i & 31)];
            kfS[i >> 5][i & 31] = RATIO * (__expf(raw - kmax) + FEPS);
        }
        for (int i = t; i < 32 * 64; i += 256)
            vS[i >> 6][i & 63] = vb[(size_t)(n0 + (i >> 6)) * DIMc + (i & 63)];
        __syncthreads();

        if (t < 32) {            // column sums -> k_cumsum partial
            float s = 0.f;
#pragma unroll
            for (int nn = 0; nn < 32; nn++) s += kfS[nn][t];
            skcs += s;
        }
#pragma unroll
        for (int nn = 0; nn < 32; nn++) {
            float vv = vS[nn][e];
#pragma unroll
            for (int i = 0; i < 8; i++)
                acc[i] = fmaf(kfS[nn][mg + 4 * i], vv, acc[i]);
        }
        __syncthreads();
    }
#pragma unroll
    for (int i = 0; i < 8; i++)
        g_ctxp[((size_t)bh * NSEG + seg) * (Mm * DHh) + (mg + 4 * i) * DHh + e] = acc[i];
    if (t < 32)
        g_kcsp[(bh * NSEG + seg) * Mm + t] = skcs;
}

// reduce ctx partials and kcs partials (fixed order -> deterministic)
__global__ __launch_bounds__(256)
void ctx_reduce_kernel()
{
    const int bh = blockIdx.x;
    for (int i = threadIdx.x; i < Mm * DHh; i += 256) {
        float s = 0.f;
#pragma unroll
        for (int g = 0; g < NSEG; g++)
            s += g_ctxp[((size_t)bh * NSEG + g) * (Mm * DHh) + i];
        g_ctx[(size_t)bh * (Mm * DHh) + i] = s;
    }
    if (threadIdx.x < Mm) {
        float s = 0.f;
#pragma unroll
        for (int g = 0; g < NSEG; g++)
            s += g_kcsp[(bh * NSEG + g) * Mm + threadIdx.x];
        g_kcs[bh * Mm + threadIdx.x] = s;
    }
}

__global__ __launch_bounds__(256)
void attn_out_kernel(__nv_bfloat16* __restrict__ oh, __nv_bfloat16* __restrict__ ol)
{
    __shared__ float ctxS[Mm][DHh];
    __shared__ float kcsS[Mm];

    const int tid = threadIdx.x;
    const int warp = tid >> 5, lane = tid & 31;
    const int r = blockIdx.x * 8 + warp;
    const int bh = r >> 12;
    const int n  = r & (Nn - 1);
    const int b  = bh >> 4, h = bh & 15;

    for (int i = tid; i < Mm * DHh; i += 256)
        ctxS[i >> 6][i & 63] = g_ctx[(size_t)bh * (Mm * DHh) + i];
    if (tid < Mm) kcsS[tid] = g_kcs[bh * Mm + tid];
    __syncthreads();

    float myqf = g_qf[(size_t)r * Mm + lane];
    float D = myqf * kcsS[lane];
#pragma unroll
    for (int o = 16; o > 0; o >>= 1) D += __shfl_xor_sync(0xffffffffu, D, o);
    float Dinv = 1.0f / D;

    float o0 = 0.f, o1 = 0.f;
#pragma unroll
    for (int m = 0; m < Mm; m++) {
        float qv = __shfl_sync(0xffffffffu, myqf, m);
        o0 = fmaf(qv, ctxS[m][lane], o0);
        o1 = fmaf(qv, ctxS[m][lane + 32], o1);
    }
    o0 *= Dinv; o1 *= Dinv;

    size_t base = (size_t)(b * Nn + n) * DIMc + h * DHh;
    __nv_bfloat16 h0 = __float2bfloat16_rn(o0);
    __nv_bfloat16 h1 = __float2bfloat16_rn(o1);
    oh[base + lane]      = h0;
    oh[base + lane + 32] = h1;
    ol[base + lane]      = __float2bfloat16_rn(o0 - __bfloat162float(h0));
    ol[base + lane + 32] = __float2bfloat16_rn(o1 - __bfloat162float(h1));
}

// ==================== launch ====================
extern "C" void kernel_launch(void* const* d_in, const int* in_sizes, int n_in,
                              void* d_out, int out_size)
{
    const float*         x    = (const float*)d_in[0];
    const unsigned char* mask = (const unsigned char*)d_in[1];
    const float*         proj = (const float*)d_in[2];
    const float* Wq = (const float*)d_in[3];
    const float* bq = (const float*)d_in[4];
    const float* Wk = (const float*)d_in[5];
    const float* bk = (const float*)d_in[6];
    const float* Wv = (const float*)d_in[7];
    const float* bv = (const float*)d_in[8];
    const float* Wo = (const float*)d_in[9];
    const float* bo = (const float*)d_in[10];
    float* out = (float*)d_out;

    float *v_;
    __nv_bfloat16 *xh_, *xl_, *wth_, *wtl_;
    cudaGetSymbolAddress((void**)&v_,   g_v);
    cudaGetSymbolAddress((void**)&xh_,  g_xh);
    cudaGetSymbolAddress((void**)&xl_,  g_xl);
    cudaGetSymbolAddress((void**)&wth_, g_wth);
    cudaGetSymbolAddress((void**)&wtl_, g_wtl);

    cudaFuncSetAttribute(gemm_qkv_kernel,
                         cudaFuncAttributeMaxDynamicSharedMemorySize, GEMM_SMEM_BYTES);
    cudaFuncSetAttribute(gemm_o_kernel,
                         cudaFuncAttributeMaxDynamicSharedMemorySize, GEMM_SMEM_BYTES);

    const size_t WSZ = (size_t)DIMc * DIMc;
    const int nElem = Bz * Nn * DIMc;
    dim3 gSplitT(32, 32);

    split_kernel<<<nElem / (256 * 4), 256>>>((const float4*)x,
        (__nv_bfloat162*)xh_, (__nv_bfloat162*)xl_);
    splitT_kernel<<<gSplitT, 256>>>(Wq, wth_ + 0*WSZ, wtl_ + 0*WSZ);
    splitT_kernel<<<gSplitT, 256>>>(Wk, wth_ + 1*WSZ, wtl_ + 1*WSZ);
    splitT_kernel<<<gSplitT, 256>>>(Wv, wth_ + 2*WSZ, wtl_ + 2*WSZ);
    splitT_kernel<<<gSplitT, 256>>>(Wo, wth_ + 3*WSZ, wtl_ + 3*WSZ);
    init_kmax_kernel<<<1, Bz * Hh>>>();

    gemm_qkv_kernel<<<dim3(24, 128), 256, GEMM_SMEM_BYTES>>>(
        xh_, xl_, wth_, wtl_, bq, bk, bv, mask, proj, v_);

    context_part_kernel<<<dim3(Bz * Hh, NSEG), 256>>>();
    ctx_reduce_kernel<<<Bz * Hh, 256>>>();
    attn_out_kernel<<<(Bz * Hh * Nn) / 8, 256>>>(xh_, xl_);

    gemm_o_kernel<<<dim3(8, 128), 256, GEMM_SMEM_BYTES>>>(
        xh_, xl_, wth_ + 3*WSZ, wtl_ + 3*WSZ, bo, out);
}